// round 6
// baseline (speedup 1.0000x reference)
#include <cuda_runtime.h>
#include <math_constants.h>
#include <cstdint>

#define CCH 256
#define HW  65536     // 256*256 pixels
#define P_TILE 32

// ---------------- scratch (no allocations allowed) ----------------
__device__ float g_X[CCH * 256];        // X[c][n]
__device__ float g_XT[256 * CCH];       // XT[n][c] = X[c][n]
__device__ float g_protoC2[256 * CCH];  // protoC2[slot][c]  compacted normalized protos
__device__ float g_mlo[CCH], g_mdi[CCH], g_mhi[CCH];
__device__ float g_sel[256];
__device__ int   g_slot[256];
__device__ int   g_selidx[256];
__device__ int   g_S;

// ---------------- helpers ----------------
__device__ __forceinline__ float warp_sum(float v) {
#pragma unroll
    for (int o = 16; o; o >>= 1) v += __shfl_xor_sync(0xffffffffu, v, o);
    return v;
}
__device__ __forceinline__ float warp_max(float v) {
#pragma unroll
    for (int o = 16; o; o >>= 1) v = fmaxf(v, __shfl_xor_sync(0xffffffffu, v, o));
    return v;
}
__device__ __forceinline__ float blk_sum256(float v, float* s, int t) {
    v = warp_sum(v);
    __syncthreads();
    if ((t & 31) == 0) s[t >> 5] = v;
    __syncthreads();
    if (t < 32) {
        float x = (t < 8) ? s[t] : 0.f;
        x = warp_sum(x);
        if (t == 0) s[32] = x;
    }
    __syncthreads();
    float r = s[32];
    __syncthreads();
    return r;
}

// exp(x) for x <= 0 on the FMA pipe (no MUFU)
__device__ __forceinline__ float fast_exp_neg(float x) {
    float t = x * 1.44269504088896340736f;
    float n = rintf(t);
    float r = t - n;
    float p = 1.540353039338161e-4f;
    p = fmaf(p, r, 1.3333558146428443e-3f);
    p = fmaf(p, r, 9.618129107628477e-3f);
    p = fmaf(p, r, 5.550410866482158e-2f);
    p = fmaf(p, r, 2.402265069591007e-1f);
    p = fmaf(p, r, 6.931471805599453e-1f);
    p = fmaf(p, r, 1.0f);
    float s = __int_as_float(((int)n + 127) << 23);
    return p * s;
}

// ---------------- K1a: pool sup_x -> g_X[c][n] and g_XT[n][c] ----------------
__global__ void pool_x_kernel(const float* __restrict__ sx) {
    int c = blockIdx.x, t = threadIdx.x;
    const float* base = sx + (size_t)c * HW + t;
    __shared__ float sm[16 * 256];
#pragma unroll
    for (int bh = 0; bh < 16; bh++) {
        float a = 0.f;
#pragma unroll
        for (int r = 0; r < 16; r++) a += base[(bh * 16 + r) * 256];
        sm[bh * 256 + t] = a;
    }
    __syncthreads();
    int bh = t >> 4, bw = t & 15;
    float s = 0.f;
#pragma unroll
    for (int k = 0; k < 16; k++) s += sm[bh * 256 + bw * 16 + k];
    float v = s * (1.f / 256.f);
    g_X[c * 256 + t] = v;
    g_XT[t * 256 + c] = v;
}

// ---------------- K1b: pool sup_y -> sel[n] ----------------
__global__ void pool_y_kernel(const float* __restrict__ sy) {
    int t = threadIdx.x;
    const float* base = sy + t;
    __shared__ float sm[16 * 256];
#pragma unroll
    for (int bh = 0; bh < 16; bh++) {
        float a = 0.f;
#pragma unroll
        for (int r = 0; r < 16; r++) a += base[(bh * 16 + r) * 256];
        sm[bh * 256 + t] = a;
    }
    __syncthreads();
    int bh = t >> 4, bw = t & 15;
    float s = 0.f;
#pragma unroll
    for (int k = 0; k < 16; k++) s += sm[bh * 256 + bw * 16 + k];
    g_sel[t] = ((s * (1.f / 256.f)) > 0.5f) ? 1.f : 0.f;
}

// ---------------- K1c: prefix scan -> compaction maps ----------------
__global__ void selscan_kernel() {
    int t = threadIdx.x;
    __shared__ int ps[256];
    int s = (g_sel[t] > 0.f) ? 1 : 0;
    ps[t] = s;
    g_selidx[t] = 0;
    __syncthreads();
    if (t == 0) {
        int acc = 0;
        for (int n = 0; n < 256; n++) { int v = ps[n]; ps[n] = acc; acc += v; }
        g_S = acc;
    }
    __syncthreads();
    g_slot[t] = ps[t];
    if (s) g_selidx[ps[t]] = t;
}

// ---------------- K2: w1 rows + softmax -> tridiagonal band ----------------
#define BK_ROWS 2
__global__ __launch_bounds__(256) void band_kernel(const float* __restrict__ cal) {
    int t = threadIdx.x;
    int i0 = blockIdx.x * BK_ROWS;
    __shared__ float tile[256 * 33];
    __shared__ float wrow[BK_ROWS][256];
    float acc[BK_ROWS];
#pragma unroll
    for (int i = 0; i < BK_ROWS; i++) acc[i] = 0.f;

    for (int k0 = 0; k0 < 256; k0 += 32) {
        __syncthreads();
#pragma unroll
        for (int it = 0; it < 32; it++) {
            int idx = t + it * 256;
            int r = idx >> 5, kk = idx & 31;
            tile[r * 33 + kk] = g_X[r * 256 + k0 + kk];
        }
        __syncthreads();
        float own[32];
#pragma unroll
        for (int kk = 0; kk < 32; kk++) own[kk] = tile[t * 33 + kk];
#pragma unroll
        for (int i = 0; i < BK_ROWS; i++) {
            const float* xi = &tile[(i0 + i) * 33];
            float a = acc[i];
#pragma unroll
            for (int kk = 0; kk < 32; kk++) a = fmaf(own[kk], xi[kk], a);
            acc[i] = a;
        }
    }
#pragma unroll
    for (int i = 0; i < BK_ROWS; i++) wrow[i][t] = acc[i];
    __syncthreads();

    int w = t >> 5, lane = t & 31;
    if (w < BK_ROWS) {
        int i = i0 + w;
        float mx = -CUDART_INF_F;
#pragma unroll
        for (int k = 0; k < 8; k++) mx = fmaxf(mx, wrow[w][k * 32 + lane]);
        mx = warp_max(mx);
        float s = 0.f;
#pragma unroll
        for (int k = 0; k < 8; k++) s += expf(wrow[w][k * 32 + lane] - mx);
        s = warp_sum(s);
        if (lane == 0) {
            float inv = 1.f / s;
            if (i > 0) {
                float e = expf(wrow[w][i - 1] - mx) * inv;
                g_mlo[i] = cal[i * 256 + (i - 1)] * (1.f + 0.2f * e);
            } else g_mlo[0] = 0.f;
            {
                float e = expf(wrow[w][i] - mx) * inv;
                g_mdi[i] = cal[i * 256 + i] * (1.f + 0.2f * e);
            }
            if (i < 255) {
                float e = expf(wrow[w][i + 1] - mx) * inv;
                g_mhi[i] = cal[i * 256 + (i + 1)] * (1.f + 0.2f * e);
            } else g_mhi[255] = 0.f;
        }
    }
}

// ---------------- K3: tridiag apply + col-normalize -> protoC2[slot][c] ----------------
__global__ void proto_kernel() {
    int n = blockIdx.x, i = threadIdx.x;
    __shared__ float xr[258];
    __shared__ float sred[40];
    xr[i + 1] = g_XT[n * 256 + i];          // coalesced row read
    if (i == 0) { xr[0] = 0.f; xr[257] = 0.f; }
    __syncthreads();
    float v = g_mlo[i] * xr[i] + g_mdi[i] * xr[i + 1] + g_mhi[i] * xr[i + 2];
    float ss = blk_sum256(v * v, sred, i);
    float nr = fmaxf(sqrtf(ss), 1e-4f);
    if (g_sel[n] > 0.f) g_protoC2[g_slot[n] * 256 + i] = v / nr;   // coalesced row write
}

// ---------------- K4: fused dists + softmax + pred + argmax ----------------
// 32 pixels per CTA. Thread owns a slot-QUAD (4 protos) and a c-range;
// q LDS amortized 4x over slots. Adaptive split: UG2 = pow2 >= ceil(S/4),
// cgroups = 256/UG2; all 256 threads active. Partials reduced via smem tree.
__global__ __launch_bounds__(256) void dist_kernel(const float* __restrict__ qry,
                                                   float* __restrict__ out) {
    int t = threadIdx.x;
    int p0 = blockIdx.x * P_TILE;
    __shared__ __align__(16) float buf[256 * P_TILE];   // 32KB: q -> partials -> d
    __shared__ float partialn[256];
    __shared__ float nrm[P_TILE];
    __shared__ int sidx[256];
    __shared__ int sS;

    if (t == 0) sS = g_S;
    sidx[t] = g_selidx[t];

    // q tile load (coalesced) + per-pixel sumsq. buf[c*32 + j]
    float ss = 0.f;
#pragma unroll
    for (int r = 0; r < 32; r++) {
        int idx = r * 256 + t;
        float v = qry[(size_t)(idx >> 5) * HW + p0 + (idx & 31)];
        buf[idx] = v;
        ss += v * v;
    }
    partialn[t] = ss;
    __syncthreads();
    if (t < 32) {
        float s = 0.f;
#pragma unroll
        for (int k = 0; k < 8; k++) s += partialn[t + 32 * k];
        nrm[t] = fmaxf(sqrtf(s), 1e-4f);
    }

    int S = sS;
    int need = (S + 3) >> 2;
    int UG2 = 1;
    while (UG2 < need) UG2 <<= 1;          // 1..64
    int cgroups = 256 / UG2;               // 4..256
    int cpt = 256 / cgroups;               // c per thread
    int u = t & (UG2 - 1);
    int cg = t / UG2;
    int cbeg = cg * cpt, cend = cbeg + cpt;
    int s0 = 4 * u;

    unsigned long long acc[4][16];
#pragma unroll
    for (int k = 0; k < 4; k++)
#pragma unroll
        for (int j = 0; j < 16; j++) acc[k][j] = 0ull;

    if (S > 0) {
        const float* pb0 = g_protoC2 + (s0 + 0) * 256;
        const float* pb1 = g_protoC2 + (s0 + 1) * 256;
        const float* pb2 = g_protoC2 + (s0 + 2) * 256;
        const float* pb3 = g_protoC2 + (s0 + 3) * 256;
#pragma unroll 2
        for (int c0 = cbeg; c0 < cend; c0 += 4) {
            float4 pr[4];
            pr[0] = *(const float4*)(pb0 + c0);
            pr[1] = *(const float4*)(pb1 + c0);
            pr[2] = *(const float4*)(pb2 + c0);
            pr[3] = *(const float4*)(pb3 + c0);
#pragma unroll
            for (int cc = 0; cc < 4; cc++) {
                const ulonglong2* q2 = (const ulonglong2*)(buf + (c0 + cc) * P_TILE);
                ulonglong2 qq[8];
#pragma unroll
                for (int l = 0; l < 8; l++) qq[l] = q2[l];
#pragma unroll
                for (int k = 0; k < 4; k++) {
                    float pv = (cc == 0) ? pr[k].x : (cc == 1) ? pr[k].y : (cc == 2) ? pr[k].z : pr[k].w;
                    unsigned int pu = __float_as_uint(pv);
                    unsigned long long pt2;
                    asm("mov.b64 %0, {%1, %2};" : "=l"(pt2) : "r"(pu), "r"(pu));
#pragma unroll
                    for (int l = 0; l < 8; l++) {
                        asm("fma.rn.f32x2 %0, %1, %2, %0;" : "+l"(acc[k][2 * l])     : "l"(qq[l].x), "l"(pt2));
                        asm("fma.rn.f32x2 %0, %1, %2, %0;" : "+l"(acc[k][2 * l + 1]) : "l"(qq[l].y), "l"(pt2));
                    }
                }
            }
        }
    }
    __syncthreads();   // q reads complete; buf reusable

    // tree-reduce partials over cg in 2 slot-chunks (<=32KB staging in buf)
    unsigned long long* pbuf = (unsigned long long*)buf;
    for (int h = cgroups >> 1; h >= 1; h >>= 1) {
#pragma unroll
        for (int half = 0; half < 2; half++) {
            if (cg >= h && cg < 2 * h) {
                int base = ((cg - h) * UG2 + u) * 32;
#pragma unroll
                for (int k = 0; k < 2; k++)
#pragma unroll
                    for (int j = 0; j < 16; j++)
                        pbuf[base + k * 16 + j] = acc[2 * half + k][j];
            }
            __syncthreads();
            if (cg < h) {
                int base = (cg * UG2 + u) * 32;
#pragma unroll
                for (int k = 0; k < 2; k++)
#pragma unroll
                    for (int j = 0; j < 16; j++) {
                        unsigned long long o = pbuf[base + k * 16 + j];
                        asm("add.rn.f32x2 %0, %0, %1;" : "+l"(acc[2 * half + k][j]) : "l"(o));
                    }
            }
            __syncthreads();
        }
    }

    // owners (cg==0) scale and write d[px][slot] into buf
    const float NEG = -1e9f;
    if (cg == 0 && S > 0) {
#pragma unroll
        for (int k = 0; k < 4; k++) {
            int slot = s0 + k;
            bool ok = (slot < S);
#pragma unroll
            for (int j = 0; j < 16; j++) {
                unsigned int lo, hi;
                asm("mov.b64 {%0, %1}, %2;" : "=r"(lo), "=r"(hi) : "l"(acc[k][j]));
                int pj0 = 2 * j, pj1 = 2 * j + 1;
                buf[pj0 * 256 + slot] = ok ? __uint_as_float(lo) * (20.f / nrm[pj0]) : NEG;
                buf[pj1 * 256 + slot] = ok ? __uint_as_float(hi) * (20.f / nrm[pj1]) : NEG;
            }
        }
    }
    __syncthreads();

    // per-pixel softmax-weighted sum + first-tie argmax over selected slots
    int w = t >> 5, lane = t & 31;
    int kmax = (S + 31) >> 5;
    for (int pix = w; pix < P_TILE; pix += 8) {
        if (S == 0) {
            if (lane == 0) { out[p0 + pix] = NEG; out[HW + p0 + pix] = 0.f; }
            continue;
        }
        const float* dp = buf + pix * 256;
        float bm = -CUDART_INF_F; int bi = 0;
        for (int k = 0; k < kmax; k++) {
            int n = k * 32 + lane;
            float v = (n < S) ? dp[n] : -CUDART_INF_F;
            if (v > bm) { bm = v; bi = n; }
        }
#pragma unroll
        for (int o = 16; o; o >>= 1) {
            float om = __shfl_xor_sync(0xffffffffu, bm, o);
            int   oi = __shfl_xor_sync(0xffffffffu, bi, o);
            if (om > bm || (om == bm && oi < bi)) { bm = om; bi = oi; }
        }
        float se = 0.f, sd = 0.f;
        for (int k = 0; k < kmax; k++) {
            int n = k * 32 + lane;
            if (n < S) {
                float v = dp[n];
                float e = fast_exp_neg(v - bm);
                se += e; sd += e * v;
            }
        }
        se = warp_sum(se); sd = warp_sum(sd);
        if (lane == 0) {
            out[p0 + pix]      = sd / se;
            out[HW + p0 + pix] = (float)sidx[bi];
        }
    }
}

// ---------------- launcher ----------------
extern "C" void kernel_launch(void* const* d_in, const int* in_sizes, int n_in,
                              void* d_out, int out_size) {
    const float* qry   = (const float*)d_in[0];
    const float* sup_x = (const float*)d_in[1];
    const float* sup_y = (const float*)d_in[2];
    const float* cal   = (const float*)d_in[4];
    float* out = (float*)d_out;

    pool_x_kernel<<<256, 256>>>(sup_x);
    pool_y_kernel<<<1, 256>>>(sup_y);
    selscan_kernel<<<1, 256>>>();
    band_kernel<<<128, 256>>>(cal);
    proto_kernel<<<256, 256>>>();
    dist_kernel<<<HW / P_TILE, 256>>>(qry, out);
}

// round 7
// speedup vs baseline: 2.9602x; 2.9602x over previous
#include <cuda_runtime.h>
#include <math_constants.h>
#include <cstdint>

#define CCH 256
#define HW  65536     // 256*256 pixels
#define P_TILE 32

// ---------------- scratch (no allocations allowed) ----------------
__device__ float g_X[CCH * 256];       // X[c][n]
__device__ float g_protoC[CCH * 256];  // protoC[c][slot]  compacted normalized protos
__device__ float g_mlo[CCH], g_mdi[CCH], g_mhi[CCH];
__device__ float g_sel[256];
__device__ int   g_slot[256];
__device__ int   g_selidx[256];
__device__ int   g_S;

// ---------------- helpers ----------------
__device__ __forceinline__ float warp_sum(float v) {
#pragma unroll
    for (int o = 16; o; o >>= 1) v += __shfl_xor_sync(0xffffffffu, v, o);
    return v;
}
__device__ __forceinline__ float warp_max(float v) {
#pragma unroll
    for (int o = 16; o; o >>= 1) v = fmaxf(v, __shfl_xor_sync(0xffffffffu, v, o));
    return v;
}
__device__ __forceinline__ float blk_sum256(float v, float* s, int t) {
    v = warp_sum(v);
    __syncthreads();
    if ((t & 31) == 0) s[t >> 5] = v;
    __syncthreads();
    if (t < 32) {
        float x = (t < 8) ? s[t] : 0.f;
        x = warp_sum(x);
        if (t == 0) s[32] = x;
    }
    __syncthreads();
    float r = s[32];
    __syncthreads();
    return r;
}

// exp(x) for x <= 0 on the FMA pipe (no MUFU)
__device__ __forceinline__ float fast_exp_neg(float x) {
    float t = x * 1.44269504088896340736f;
    float n = rintf(t);
    float r = t - n;
    float p = 1.540353039338161e-4f;
    p = fmaf(p, r, 1.3333558146428443e-3f);
    p = fmaf(p, r, 9.618129107628477e-3f);
    p = fmaf(p, r, 5.550410866482158e-2f);
    p = fmaf(p, r, 2.402265069591007e-1f);
    p = fmaf(p, r, 6.931471805599453e-1f);
    p = fmaf(p, r, 1.0f);
    float s = __int_as_float(((int)n + 127) << 23);
    return p * s;
}

// ---------------- K1a: pool sup_x -> g_X[c][n] ----------------
__global__ void pool_x_kernel(const float* __restrict__ sx) {
    int c = blockIdx.x, t = threadIdx.x;
    const float* base = sx + (size_t)c * HW + t;
    __shared__ float sm[16 * 256];
#pragma unroll
    for (int bh = 0; bh < 16; bh++) {
        float a = 0.f;
#pragma unroll
        for (int r = 0; r < 16; r++) a += base[(bh * 16 + r) * 256];
        sm[bh * 256 + t] = a;
    }
    __syncthreads();
    int bh = t >> 4, bw = t & 15;
    float s = 0.f;
#pragma unroll
    for (int k = 0; k < 16; k++) s += sm[bh * 256 + bw * 16 + k];
    g_X[c * 256 + t] = s * (1.f / 256.f);
}

// ---------------- K1b: pool sup_y -> sel[n] ----------------
__global__ void pool_y_kernel(const float* __restrict__ sy) {
    int t = threadIdx.x;
    const float* base = sy + t;
    __shared__ float sm[16 * 256];
#pragma unroll
    for (int bh = 0; bh < 16; bh++) {
        float a = 0.f;
#pragma unroll
        for (int r = 0; r < 16; r++) a += base[(bh * 16 + r) * 256];
        sm[bh * 256 + t] = a;
    }
    __syncthreads();
    int bh = t >> 4, bw = t & 15;
    float s = 0.f;
#pragma unroll
    for (int k = 0; k < 16; k++) s += sm[bh * 256 + bw * 16 + k];
    g_sel[t] = ((s * (1.f / 256.f)) > 0.5f) ? 1.f : 0.f;
}

// ---------------- K1c: prefix scan -> compaction maps ----------------
__global__ void selscan_kernel() {
    int t = threadIdx.x;
    __shared__ int ps[256];
    int s = (g_sel[t] > 0.f) ? 1 : 0;
    ps[t] = s;
    g_selidx[t] = 0;
    __syncthreads();
    if (t == 0) {
        int acc = 0;
        for (int n = 0; n < 256; n++) { int v = ps[n]; ps[n] = acc; acc += v; }
        g_S = acc;
    }
    __syncthreads();
    g_slot[t] = ps[t];
    if (s) g_selidx[ps[t]] = t;
}

// ---------------- K2: w1 rows + softmax -> tridiagonal band (R4 config) ----------------
#define BK_ROWS 4
__global__ __launch_bounds__(256) void band_kernel(const float* __restrict__ cal) {
    int t = threadIdx.x;
    int i0 = blockIdx.x * BK_ROWS;
    __shared__ float tile[256 * 33];
    __shared__ float wrow[BK_ROWS][256];
    float acc[BK_ROWS] = {0.f, 0.f, 0.f, 0.f};

    for (int k0 = 0; k0 < 256; k0 += 32) {
        __syncthreads();
#pragma unroll
        for (int it = 0; it < 32; it++) {
            int idx = t + it * 256;
            int r = idx >> 5, kk = idx & 31;
            tile[r * 33 + kk] = g_X[r * 256 + k0 + kk];
        }
        __syncthreads();
        float own[32];
#pragma unroll
        for (int kk = 0; kk < 32; kk++) own[kk] = tile[t * 33 + kk];
#pragma unroll
        for (int i = 0; i < BK_ROWS; i++) {
            const float* xi = &tile[(i0 + i) * 33];
            float a = acc[i];
#pragma unroll
            for (int kk = 0; kk < 32; kk++) a = fmaf(own[kk], xi[kk], a);
            acc[i] = a;
        }
    }
#pragma unroll
    for (int i = 0; i < BK_ROWS; i++) wrow[i][t] = acc[i];
    __syncthreads();

    int w = t >> 5, lane = t & 31;
    if (w < BK_ROWS) {
        int i = i0 + w;
        float mx = -CUDART_INF_F;
#pragma unroll
        for (int k = 0; k < 8; k++) mx = fmaxf(mx, wrow[w][k * 32 + lane]);
        mx = warp_max(mx);
        float s = 0.f;
#pragma unroll
        for (int k = 0; k < 8; k++) s += expf(wrow[w][k * 32 + lane] - mx);
        s = warp_sum(s);
        if (lane == 0) {
            float inv = 1.f / s;
            if (i > 0) {
                float e = expf(wrow[w][i - 1] - mx) * inv;
                g_mlo[i] = cal[i * 256 + (i - 1)] * (1.f + 0.2f * e);
            } else g_mlo[0] = 0.f;
            {
                float e = expf(wrow[w][i] - mx) * inv;
                g_mdi[i] = cal[i * 256 + i] * (1.f + 0.2f * e);
            }
            if (i < 255) {
                float e = expf(wrow[w][i + 1] - mx) * inv;
                g_mhi[i] = cal[i * 256 + (i + 1)] * (1.f + 0.2f * e);
            } else g_mhi[255] = 0.f;
        }
    }
}

// ---------------- K3: tridiag apply + col-normalize -> protoC[c][slot] ----------------
__global__ void proto_kernel() {
    int n = blockIdx.x, i = threadIdx.x;
    __shared__ float sred[40];
    float x0 = g_X[i * 256 + n];
    float xm = (i > 0)   ? g_X[(i - 1) * 256 + n] : 0.f;
    float xp = (i < 255) ? g_X[(i + 1) * 256 + n] : 0.f;
    float v = g_mlo[i] * xm + g_mdi[i] * x0 + g_mhi[i] * xp;
    float ss = blk_sum256(v * v, sred, i);
    float nrm = fmaxf(sqrtf(ss), 1e-4f);
    if (g_sel[n] > 0.f) g_protoC[i * 256 + g_slot[n]] = v / nrm;
}

// ---------------- K4: fused dists + softmax + pred + argmax ----------------
// 32 pixels per CTA. Each thread owns a slot PAIR and one c-half; q LDS shared
// by both slots (2x fewer LDS.128 than R4). pairs = ceil(S/2) <= 128 so the
// two-group map works for every S. acc = 2x16 ull = 64 regs (no spill).
__global__ __launch_bounds__(256) void dist_kernel(const float* __restrict__ qry,
                                                   float* __restrict__ out) {
    int t = threadIdx.x;
    int p0 = blockIdx.x * P_TILE;
    __shared__ __align__(16) float buf[256 * P_TILE];   // 32KB: q -> partials -> d
    __shared__ float partialn[256];
    __shared__ float nrm[P_TILE];
    __shared__ int sidx[256];
    __shared__ int sS;

    if (t == 0) sS = g_S;
    sidx[t] = g_selidx[t];

    // q tile load (coalesced) + per-pixel sumsq. buf[c*32 + j]
    float ss = 0.f;
#pragma unroll
    for (int r = 0; r < 32; r++) {
        int idx = r * 256 + t;
        float v = qry[(size_t)(idx >> 5) * HW + p0 + (idx & 31)];
        buf[idx] = v;
        ss += v * v;
    }
    partialn[t] = ss;
    __syncthreads();
    if (t < 32) {
        float s = 0.f;
#pragma unroll
        for (int k = 0; k < 8; k++) s += partialn[t + 32 * k];
        nrm[t] = fmaxf(sqrtf(s), 1e-4f);
    }

    int S = sS;
    int pairs = (S + 1) >> 1;              // <= 128
    int group = -1, u = 0;
    if (t < pairs)                    { group = 0; u = t; }
    else if (t >= 128 && t < 128 + pairs) { group = 1; u = t - 128; }
    int cbeg = (group == 1) ? 128 : 0;
    int cend = cbeg + 128;

    unsigned long long acc[2][16];
#pragma unroll
    for (int k = 0; k < 2; k++)
#pragma unroll
        for (int j = 0; j < 16; j++) acc[k][j] = 0ull;

    if (group >= 0) {
        const float2* pp = (const float2*)(g_protoC + 2 * u);
#pragma unroll 4
        for (int c = cbeg; c < cend; c++) {
            float2 pt = __ldg(pp + (c << 7));      // protoC[c][2u..2u+1]
            unsigned long long pa, pb;
            unsigned int pxu = __float_as_uint(pt.x), pyu = __float_as_uint(pt.y);
            asm("mov.b64 %0, {%1, %2};" : "=l"(pa) : "r"(pxu), "r"(pxu));
            asm("mov.b64 %0, {%1, %2};" : "=l"(pb) : "r"(pyu), "r"(pyu));
            const ulonglong2* q2 = (const ulonglong2*)(buf + c * P_TILE);
#pragma unroll
            for (int l = 0; l < 8; l++) {
                ulonglong2 q = q2[l];
                asm("fma.rn.f32x2 %0, %1, %2, %0;" : "+l"(acc[0][2 * l])     : "l"(q.x), "l"(pa));
                asm("fma.rn.f32x2 %0, %1, %2, %0;" : "+l"(acc[0][2 * l + 1]) : "l"(q.y), "l"(pa));
                asm("fma.rn.f32x2 %0, %1, %2, %0;" : "+l"(acc[1][2 * l])     : "l"(q.x), "l"(pb));
                asm("fma.rn.f32x2 %0, %1, %2, %0;" : "+l"(acc[1][2 * l + 1]) : "l"(q.y), "l"(pb));
            }
        }
    }
    __syncthreads();   // q reads complete; buf reusable

    // group 1 stages its partials (pairs*32 ull <= 4096 ull = 32KB)
    unsigned long long* pbuf = (unsigned long long*)buf;
    if (group == 1) {
#pragma unroll
        for (int k = 0; k < 2; k++)
#pragma unroll
            for (int j = 0; j < 16; j++) pbuf[u * 32 + k * 16 + j] = acc[k][j];
    }
    __syncthreads();
    if (group == 0) {
#pragma unroll
        for (int k = 0; k < 2; k++)
#pragma unroll
            for (int j = 0; j < 16; j++) {
                unsigned long long o = pbuf[u * 32 + k * 16 + j];
                asm("add.rn.f32x2 %0, %0, %1;" : "+l"(acc[k][j]) : "l"(o));
            }
    }
    __syncthreads();   // partial reads done; buf becomes d-matrix

    const float NEG = -1e9f;
    // fill NEG for unselected slots (only slots >= S)
    if (t >= ((S + 1) & ~1)) {     // slots covered by pairs are written below
#pragma unroll
        for (int j = 0; j < 32; j++) buf[j * 256 + t] = NEG;
    }
    if (group == 0) {
#pragma unroll
        for (int k = 0; k < 2; k++) {
            int slot = 2 * u + k;
            bool ok = (slot < S);
#pragma unroll
            for (int j = 0; j < 16; j++) {
                unsigned int lo, hi;
                asm("mov.b64 {%0, %1}, %2;" : "=r"(lo), "=r"(hi) : "l"(acc[k][j]));
                int pj0 = 2 * j, pj1 = 2 * j + 1;
                buf[pj0 * 256 + slot] = ok ? __uint_as_float(lo) * (20.f / nrm[pj0]) : NEG;
                buf[pj1 * 256 + slot] = ok ? __uint_as_float(hi) * (20.f / nrm[pj1]) : NEG;
            }
        }
    }
    __syncthreads();

    // per-pixel softmax-weighted sum + first-tie argmax over selected slots
    int w = t >> 5, lane = t & 31;
    int kmax = (S + 31) >> 5;
    for (int pix = w; pix < P_TILE; pix += 8) {
        if (S == 0) {
            if (lane == 0) { out[p0 + pix] = NEG; out[HW + p0 + pix] = 0.f; }
            continue;
        }
        const float* dp = buf + pix * 256;
        float bm = -CUDART_INF_F; int bi = 0;
        for (int k = 0; k < kmax; k++) {
            int n = k * 32 + lane;
            float v = (n < S) ? dp[n] : -CUDART_INF_F;
            if (v > bm) { bm = v; bi = n; }
        }
#pragma unroll
        for (int o = 16; o; o >>= 1) {
            float om = __shfl_xor_sync(0xffffffffu, bm, o);
            int   oi = __shfl_xor_sync(0xffffffffu, bi, o);
            if (om > bm || (om == bm && oi < bi)) { bm = om; bi = oi; }
        }
        float se = 0.f, sd = 0.f;
        for (int k = 0; k < kmax; k++) {
            int n = k * 32 + lane;
            if (n < S) {
                float v = dp[n];
                float e = fast_exp_neg(v - bm);
                se += e; sd += e * v;
            }
        }
        se = warp_sum(se); sd = warp_sum(sd);
        if (lane == 0) {
            out[p0 + pix]      = sd / se;
            out[HW + p0 + pix] = (float)sidx[bi];
        }
    }
}

// ---------------- launcher ----------------
extern "C" void kernel_launch(void* const* d_in, const int* in_sizes, int n_in,
                              void* d_out, int out_size) {
    const float* qry   = (const float*)d_in[0];
    const float* sup_x = (const float*)d_in[1];
    const float* sup_y = (const float*)d_in[2];
    const float* cal   = (const float*)d_in[4];
    float* out = (float*)d_out;

    pool_x_kernel<<<256, 256>>>(sup_x);
    pool_y_kernel<<<1, 256>>>(sup_y);
    selscan_kernel<<<1, 256>>>();
    band_kernel<<<64, 256>>>(cal);
    proto_kernel<<<256, 256>>>();
    dist_kernel<<<HW / P_TILE, 256>>>(qry, out);
}

// round 8
// speedup vs baseline: 4.1913x; 1.4159x over previous
#include <cuda_runtime.h>
#include <math_constants.h>
#include <cstdint>

#define CCH 256
#define HW  65536     // 256*256 pixels
#define P_TILE 32

// ---------------- scratch (no allocations allowed) ----------------
__device__ float g_X[CCH * 256];       // X[c][n]
__device__ float g_protoC[CCH * 256];  // protoC[c][slot]  compacted normalized protos
__device__ float g_mlo[CCH], g_mdi[CCH], g_mhi[CCH];
__device__ float g_sel[256];
__device__ int   g_slot[256];
__device__ int   g_selidx[256];
__device__ int   g_S;

// ---------------- helpers ----------------
__device__ __forceinline__ float warp_sum(float v) {
#pragma unroll
    for (int o = 16; o; o >>= 1) v += __shfl_xor_sync(0xffffffffu, v, o);
    return v;
}
__device__ __forceinline__ float warp_max(float v) {
#pragma unroll
    for (int o = 16; o; o >>= 1) v = fmaxf(v, __shfl_xor_sync(0xffffffffu, v, o));
    return v;
}
__device__ __forceinline__ float blk_sum256(float v, float* s, int t) {
    v = warp_sum(v);
    __syncthreads();
    if ((t & 31) == 0) s[t >> 5] = v;
    __syncthreads();
    if (t < 32) {
        float x = (t < 8) ? s[t] : 0.f;
        x = warp_sum(x);
        if (t == 0) s[32] = x;
    }
    __syncthreads();
    float r = s[32];
    __syncthreads();
    return r;
}

// exp(x) for x <= 0 on the FMA pipe (no MUFU)
__device__ __forceinline__ float fast_exp_neg(float x) {
    float t = x * 1.44269504088896340736f;
    float n = rintf(t);
    float r = t - n;
    float p = 1.540353039338161e-4f;
    p = fmaf(p, r, 1.3333558146428443e-3f);
    p = fmaf(p, r, 9.618129107628477e-3f);
    p = fmaf(p, r, 5.550410866482158e-2f);
    p = fmaf(p, r, 2.402265069591007e-1f);
    p = fmaf(p, r, 6.931471805599453e-1f);
    p = fmaf(p, r, 1.0f);
    float s = __int_as_float(((int)n + 127) << 23);
    return p * s;
}

// ---------------- K1a: pool sup_x -> g_X[c][n] ----------------
__global__ void pool_x_kernel(const float* __restrict__ sx) {
    int c = blockIdx.x, t = threadIdx.x;
    const float* base = sx + (size_t)c * HW + t;
    __shared__ float sm[16 * 256];
#pragma unroll
    for (int bh = 0; bh < 16; bh++) {
        float a = 0.f;
#pragma unroll
        for (int r = 0; r < 16; r++) a += base[(bh * 16 + r) * 256];
        sm[bh * 256 + t] = a;
    }
    __syncthreads();
    int bh = t >> 4, bw = t & 15;
    float s = 0.f;
#pragma unroll
    for (int k = 0; k < 16; k++) s += sm[bh * 256 + bw * 16 + k];
    g_X[c * 256 + t] = s * (1.f / 256.f);
}

// ---------------- K1b: pool sup_y -> sel[n] ----------------
__global__ void pool_y_kernel(const float* __restrict__ sy) {
    int t = threadIdx.x;
    const float* base = sy + t;
    __shared__ float sm[16 * 256];
#pragma unroll
    for (int bh = 0; bh < 16; bh++) {
        float a = 0.f;
#pragma unroll
        for (int r = 0; r < 16; r++) a += base[(bh * 16 + r) * 256];
        sm[bh * 256 + t] = a;
    }
    __syncthreads();
    int bh = t >> 4, bw = t & 15;
    float s = 0.f;
#pragma unroll
    for (int k = 0; k < 16; k++) s += sm[bh * 256 + bw * 16 + k];
    g_sel[t] = ((s * (1.f / 256.f)) > 0.5f) ? 1.f : 0.f;
}

// ---------------- K1c: prefix scan -> compaction maps ----------------
__global__ void selscan_kernel() {
    int t = threadIdx.x;
    __shared__ int ps[256];
    int s = (g_sel[t] > 0.f) ? 1 : 0;
    ps[t] = s;
    g_selidx[t] = 0;
    __syncthreads();
    if (t == 0) {
        int acc = 0;
        for (int n = 0; n < 256; n++) { int v = ps[n]; ps[n] = acc; acc += v; }
        g_S = acc;
    }
    __syncthreads();
    g_slot[t] = ps[t];
    if (s) g_selidx[ps[t]] = t;
}

// ---------------- K2: w1 rows + softmax -> tridiagonal band (best-known config) ----------------
#define BK_ROWS 4
__global__ __launch_bounds__(256) void band_kernel(const float* __restrict__ cal) {
    int t = threadIdx.x;
    int i0 = blockIdx.x * BK_ROWS;
    __shared__ float tile[256 * 33];
    __shared__ float wrow[BK_ROWS][256];
    float acc[BK_ROWS] = {0.f, 0.f, 0.f, 0.f};

    for (int k0 = 0; k0 < 256; k0 += 32) {
        __syncthreads();
#pragma unroll
        for (int it = 0; it < 32; it++) {
            int idx = t + it * 256;
            int r = idx >> 5, kk = idx & 31;
            tile[r * 33 + kk] = g_X[r * 256 + k0 + kk];
        }
        __syncthreads();
        float own[32];
#pragma unroll
        for (int kk = 0; kk < 32; kk++) own[kk] = tile[t * 33 + kk];
#pragma unroll
        for (int i = 0; i < BK_ROWS; i++) {
            const float* xi = &tile[(i0 + i) * 33];
            float a = acc[i];
#pragma unroll
            for (int kk = 0; kk < 32; kk++) a = fmaf(own[kk], xi[kk], a);
            acc[i] = a;
        }
    }
#pragma unroll
    for (int i = 0; i < BK_ROWS; i++) wrow[i][t] = acc[i];
    __syncthreads();

    int w = t >> 5, lane = t & 31;
    if (w < BK_ROWS) {
        int i = i0 + w;
        float mx = -CUDART_INF_F;
#pragma unroll
        for (int k = 0; k < 8; k++) mx = fmaxf(mx, wrow[w][k * 32 + lane]);
        mx = warp_max(mx);
        float s = 0.f;
#pragma unroll
        for (int k = 0; k < 8; k++) s += expf(wrow[w][k * 32 + lane] - mx);
        s = warp_sum(s);
        if (lane == 0) {
            float inv = 1.f / s;
            if (i > 0) {
                float e = expf(wrow[w][i - 1] - mx) * inv;
                g_mlo[i] = cal[i * 256 + (i - 1)] * (1.f + 0.2f * e);
            } else g_mlo[0] = 0.f;
            {
                float e = expf(wrow[w][i] - mx) * inv;
                g_mdi[i] = cal[i * 256 + i] * (1.f + 0.2f * e);
            }
            if (i < 255) {
                float e = expf(wrow[w][i + 1] - mx) * inv;
                g_mhi[i] = cal[i * 256 + (i + 1)] * (1.f + 0.2f * e);
            } else g_mhi[255] = 0.f;
        }
    }
}

// ---------------- K3: tridiag apply + col-normalize -> protoC[c][slot] ----------------
__global__ void proto_kernel() {
    int n = blockIdx.x, i = threadIdx.x;
    __shared__ float sred[40];
    float x0 = g_X[i * 256 + n];
    float xm = (i > 0)   ? g_X[(i - 1) * 256 + n] : 0.f;
    float xp = (i < 255) ? g_X[(i + 1) * 256 + n] : 0.f;
    float v = g_mlo[i] * xm + g_mdi[i] * x0 + g_mhi[i] * xp;
    float ss = blk_sum256(v * v, sred, i);
    float nrm = fmaxf(sqrtf(ss), 1e-4f);
    if (g_sel[n] > 0.f) g_protoC[i * 256 + g_slot[n]] = v / nrm;
}

// ---------------- K4: fused dists + softmax + pred + argmax ----------------
// 32 pixels per CTA. Thread owns a slot-QUAD x 8 pixels: per c only
// 2 LDS.128 (broadcast q) + 1 LDG.128 (coalesced proto quad) + 16 FMA2.
// acc[4][4] ull = 32 regs (no spill). Map: S<=128 -> 32 quads x 4 px-groups
// x 2 c-halves (smem combine); S>128 -> 64 quads x 4 px-groups, full c.
__global__ __launch_bounds__(256) void dist_kernel(const float* __restrict__ qry,
                                                   float* __restrict__ out) {
    int t = threadIdx.x;
    int p0 = blockIdx.x * P_TILE;
    __shared__ __align__(16) float buf[256 * P_TILE];   // 32KB: q -> partials -> d
    __shared__ float partialn[256];
    __shared__ float nrm[P_TILE];
    __shared__ int sidx[256];
    __shared__ int sS;

    if (t == 0) sS = g_S;
    sidx[t] = g_selidx[t];

    // q tile load (coalesced) + per-pixel sumsq. buf[c*32 + j]
    float ss = 0.f;
#pragma unroll
    for (int r = 0; r < 32; r++) {
        int idx = r * 256 + t;
        float v = qry[(size_t)(idx >> 5) * HW + p0 + (idx & 31)];
        buf[idx] = v;
        ss += v * v;
    }
    partialn[t] = ss;
    __syncthreads();
    if (t < 32) {
        float s = 0.f;
#pragma unroll
        for (int k = 0; k < 8; k++) s += partialn[t + 32 * k];
        nrm[t] = fmaxf(sqrtf(s), 1e-4f);
    }

    int S = sS;
    bool twohalf = (S <= 128);
    int u, v, h, cbeg, cend;
    if (twohalf) {
        h = t >> 7; v = (t >> 5) & 3; u = t & 31;      // slots 4u..4u+3, px 8v..8v+7
        cbeg = h * 128; cend = cbeg + 128;
    } else {
        h = 0; v = t >> 6; u = t & 63;
        cbeg = 0; cend = 256;
    }
    int qoff = 8 * v;

    unsigned long long acc[4][4];
#pragma unroll
    for (int k = 0; k < 4; k++)
#pragma unroll
        for (int m = 0; m < 4; m++) acc[k][m] = 0ull;

    if (S > 0) {
        const float4* pp = (const float4*)(g_protoC) + u;   // element (c*256 + 4u)
#pragma unroll 4
        for (int c = cbeg; c < cend; c++) {
            float4 pr = __ldg(pp + (c << 6));
            const ulonglong2* q2 = (const ulonglong2*)(buf + c * P_TILE + qoff);
            ulonglong2 q0 = q2[0];
            ulonglong2 q1 = q2[1];
#pragma unroll
            for (int k = 0; k < 4; k++) {
                float pv = (k == 0) ? pr.x : (k == 1) ? pr.y : (k == 2) ? pr.z : pr.w;
                unsigned int pu = __float_as_uint(pv);
                unsigned long long pt2;
                asm("mov.b64 %0, {%1, %2};" : "=l"(pt2) : "r"(pu), "r"(pu));
                asm("fma.rn.f32x2 %0, %1, %2, %0;" : "+l"(acc[k][0]) : "l"(q0.x), "l"(pt2));
                asm("fma.rn.f32x2 %0, %1, %2, %0;" : "+l"(acc[k][1]) : "l"(q0.y), "l"(pt2));
                asm("fma.rn.f32x2 %0, %1, %2, %0;" : "+l"(acc[k][2]) : "l"(q1.x), "l"(pt2));
                asm("fma.rn.f32x2 %0, %1, %2, %0;" : "+l"(acc[k][3]) : "l"(q1.y), "l"(pt2));
            }
        }
    }
    __syncthreads();   // q reads complete; buf reusable

    if (twohalf) {
        // h=1 stages partials: 128 threads x 16 ull = 16KB
        unsigned long long* pbuf = (unsigned long long*)buf;
        int wv = v * 32 + u;                 // 0..127
        if (h == 1) {
#pragma unroll
            for (int k = 0; k < 4; k++)
#pragma unroll
                for (int m = 0; m < 4; m++) pbuf[wv * 16 + k * 4 + m] = acc[k][m];
        }
        __syncthreads();
        if (h == 0) {
#pragma unroll
            for (int k = 0; k < 4; k++)
#pragma unroll
                for (int m = 0; m < 4; m++) {
                    unsigned long long o = pbuf[wv * 16 + k * 4 + m];
                    asm("add.rn.f32x2 %0, %0, %1;" : "+l"(acc[k][m]) : "l"(o));
                }
        }
    }
    __syncthreads();   // staging reads done; buf becomes d-matrix

    const float NEG = -1e9f;
    bool owner = (!twohalf) || (h == 0);
    if (owner) {
#pragma unroll
        for (int k = 0; k < 4; k++) {
            int slot = 4 * u + k;
            bool ok = (slot < S);
#pragma unroll
            for (int m = 0; m < 4; m++) {
                unsigned int lo, hi;
                asm("mov.b64 {%0, %1}, %2;" : "=r"(lo), "=r"(hi) : "l"(acc[k][m]));
                int px0 = qoff + 2 * m, px1 = px0 + 1;
                buf[px0 * 256 + slot] = ok ? __uint_as_float(lo) * (20.f / nrm[px0]) : NEG;
                buf[px1 * 256 + slot] = ok ? __uint_as_float(hi) * (20.f / nrm[px1]) : NEG;
            }
        }
    }
    if (twohalf && t < 128) {               // slots 128..255 not covered by owners
        int slot = 128 + t;
#pragma unroll
        for (int j = 0; j < 32; j++) buf[j * 256 + slot] = NEG;
    }
    __syncthreads();

    // per-pixel softmax-weighted sum + first-tie argmax over selected slots
    int w = t >> 5, lane = t & 31;
    int kmax = (S + 31) >> 5;
    for (int pix = w; pix < P_TILE; pix += 8) {
        if (S == 0) {
            if (lane == 0) { out[p0 + pix] = NEG; out[HW + p0 + pix] = 0.f; }
            continue;
        }
        const float* dp = buf + pix * 256;
        float bm = -CUDART_INF_F; int bi = 0;
        for (int k = 0; k < kmax; k++) {
            int n = k * 32 + lane;
            float v2 = (n < S) ? dp[n] : -CUDART_INF_F;
            if (v2 > bm) { bm = v2; bi = n; }
        }
#pragma unroll
        for (int o = 16; o; o >>= 1) {
            float om = __shfl_xor_sync(0xffffffffu, bm, o);
            int   oi = __shfl_xor_sync(0xffffffffu, bi, o);
            if (om > bm || (om == bm && oi < bi)) { bm = om; bi = oi; }
        }
        float se = 0.f, sd = 0.f;
        for (int k = 0; k < kmax; k++) {
            int n = k * 32 + lane;
            if (n < S) {
                float v2 = dp[n];
                float e = fast_exp_neg(v2 - bm);
                se += e; sd += e * v2;
            }
        }
        se = warp_sum(se); sd = warp_sum(sd);
        if (lane == 0) {
            out[p0 + pix]      = sd / se;
            out[HW + p0 + pix] = (float)sidx[bi];
        }
    }
}

// ---------------- launcher ----------------
extern "C" void kernel_launch(void* const* d_in, const int* in_sizes, int n_in,
                              void* d_out, int out_size) {
    const float* qry   = (const float*)d_in[0];
    const float* sup_x = (const float*)d_in[1];
    const float* sup_y = (const float*)d_in[2];
    const float* cal   = (const float*)d_in[4];
    float* out = (float*)d_out;

    pool_x_kernel<<<256, 256>>>(sup_x);
    pool_y_kernel<<<1, 256>>>(sup_y);
    selscan_kernel<<<1, 256>>>();
    band_kernel<<<64, 256>>>(cal);
    proto_kernel<<<256, 256>>>();
    dist_kernel<<<HW / P_TILE, 256>>>(qry, out);
}